// round 4
// baseline (speedup 1.0000x reference)
#include <cuda_runtime.h>
#include <math.h>

#define NN   50000
#define NE   800000
#define NF   100
#define TDIM 100
#define TBL  8192

// ---------------- scratch (static __device__, no allocation) ----------------
__device__ float4 g_wl0[25], g_wl1[25], g_wr0[25], g_wr1[25];   // node attn-folded weights
__device__ float4 g_we0[25], g_we1[25];                         // edge raw-feature folded weights
__device__ float  g_weT0[TDIM], g_weT1[TDIM];                   // temporal folded weights
__device__ float  g_bl[2], g_br[2], g_be[2];
__device__ float4 g_tbl[TBL + 1];                               // {g0(x), g1(x), dg0, dg1} (b_e baked in)
__device__ float2 g_el[NN], g_er[NN];
__device__ float  g_den[2 * NN], g_num[2 * NN];

// ---------------- pass 0: fold attention vectors into fc weights ------------
__global__ void prep_kernel(const float* __restrict__ fc_node_w,
                            const float* __restrict__ fc_node_b,
                            const float* __restrict__ fc_edge_w,
                            const float* __restrict__ fc_edge_b,
                            const float* __restrict__ attn_l,
                            const float* __restrict__ attn_r,
                            const float* __restrict__ attn_e) {
    for (int t = threadIdx.x; t < 806; t += blockDim.x) {
        if (t < 200) {                                   // w_l [100][2]
            int k = t >> 1, h = t & 1;
            const float* wr = fc_node_w + k * 200 + h * 100;
            const float* a  = attn_l + h * 100;
            float s = 0.f;
            for (int f = 0; f < 100; f++) s += wr[f] * a[f];
            ((float*)(h ? g_wl1 : g_wl0))[k] = s;
        } else if (t < 400) {                            // w_r [100][2]
            int k = (t - 200) >> 1, h = t & 1;
            const float* wr = fc_node_w + k * 200 + h * 100;
            const float* a  = attn_r + h * 100;
            float s = 0.f;
            for (int f = 0; f < 100; f++) s += wr[f] * a[f];
            ((float*)(h ? g_wr1 : g_wr0))[k] = s;
        } else if (t < 800) {                            // w_e [200][2]
            int k = (t - 400) >> 1, h = t & 1;
            const float* wr = fc_edge_w + k * 200 + h * 100;
            const float* a  = attn_e + h * 100;
            float s = 0.f;
            for (int f = 0; f < 100; f++) s += wr[f] * a[f];
            if (k < 100) ((float*)(h ? g_we1 : g_we0))[k] = s;
            else         (h ? g_weT1 : g_weT0)[k - 100] = s;
        } else {                                         // biases folded
            int u = t - 800, h = u & 1;
            float s = 0.f;
            if (u < 2)      { for (int f = 0; f < 100; f++) s += fc_node_b[h*100+f] * attn_l[h*100+f]; g_bl[h] = s; }
            else if (u < 4) { for (int f = 0; f < 100; f++) s += fc_node_b[h*100+f] * attn_r[h*100+f]; g_br[h] = s; }
            else            { for (int f = 0; f < 100; f++) s += fc_edge_b[h*100+f] * attn_e[h*100+f]; g_be[h] = s; }
        }
    }
}

// ---------------- pass 0b: temporal lookup table ----------------------------
// g_h(td) = sum_j cos(td*time_w[j]+time_b[j]) * weT_h[j] + b_e[h], td in [-1,1]
__global__ void table_kernel(const float* __restrict__ time_w,
                             const float* __restrict__ time_b) {
    int i = blockIdx.x * blockDim.x + threadIdx.x;
    if (i > TBL) return;
    const float dx = 2.0f / (float)TBL;
    float x  = -1.0f + i * dx;
    float x2 = x + dx;
    float v0 = 0.f, v1 = 0.f, u0 = 0.f, u1 = 0.f;
    for (int j = 0; j < TDIM; j++) {
        float w = time_w[j], b = time_b[j];
        float c  = cosf(x  * w + b);
        float c2 = cosf(x2 * w + b);
        float e0 = g_weT0[j], e1 = g_weT1[j];
        v0 += c  * e0; v1 += c  * e1;
        u0 += c2 * e0; u1 += c2 * e1;
    }
    float b0 = g_be[0], b1 = g_be[1];
    g_tbl[i] = make_float4(v0 + b0, v1 + b1, u0 - v0, u1 - v1);
}

// ---------------- pass 0c: zero accumulators --------------------------------
__global__ void init_kernel() {
    int i = blockIdx.x * blockDim.x + threadIdx.x;
    if (i < 2 * NN) { g_den[i] = 0.f; g_num[i] = 0.f; }
}

// ---------------- pass 1: per-node el/er (warp per node) --------------------
__global__ void node_kernel(const float* __restrict__ memory) {
    int w    = (blockIdx.x * blockDim.x + threadIdx.x) >> 5;
    int lane = threadIdx.x & 31;
    if (w >= NN) return;
    float l0 = 0.f, l1 = 0.f, r0 = 0.f, r1 = 0.f;
    if (lane < 25) {
        float4 m   = ((const float4*)(memory + (size_t)w * NF))[lane];
        float4 wl0 = g_wl0[lane], wl1 = g_wl1[lane];
        float4 wr0 = g_wr0[lane], wr1 = g_wr1[lane];
        l0 = m.x*wl0.x + m.y*wl0.y + m.z*wl0.z + m.w*wl0.w;
        l1 = m.x*wl1.x + m.y*wl1.y + m.z*wl1.z + m.w*wl1.w;
        r0 = m.x*wr0.x + m.y*wr0.y + m.z*wr0.z + m.w*wr0.w;
        r1 = m.x*wr1.x + m.y*wr1.y + m.z*wr1.z + m.w*wr1.w;
    }
    #pragma unroll
    for (int o = 16; o; o >>= 1) {
        l0 += __shfl_xor_sync(0xffffffffu, l0, o);
        l1 += __shfl_xor_sync(0xffffffffu, l1, o);
        r0 += __shfl_xor_sync(0xffffffffu, r0, o);
        r1 += __shfl_xor_sync(0xffffffffu, r1, o);
    }
    if (lane == 0) {
        g_el[w] = make_float2(l0 + g_bl[0], l1 + g_bl[1]);
        g_er[w] = make_float2(r0 + g_br[0], r1 + g_br[1]);
    }
}

// ---------------- pass 2: edge sweep (warp per edge) ------------------------
__global__ void edge_kernel(const float* __restrict__ raw,
                            const float* __restrict__ edge_ts,
                            const float* __restrict__ node_ts,
                            const int*   __restrict__ src,
                            const int*   __restrict__ dst) {
    int e    = (blockIdx.x * blockDim.x + threadIdx.x) >> 5;
    int lane = threadIdx.x & 31;
    if (e >= NE) return;

    float a0 = 0.f, a1 = 0.f;
    if (lane < 25) {
        float4 r  = ((const float4*)(raw + (size_t)e * NF))[lane];
        float4 w0 = g_we0[lane];
        float4 w1 = g_we1[lane];
        a0 = r.x*w0.x + r.y*w0.y + r.z*w0.z + r.w*w0.w;
        a1 = r.x*w1.x + r.y*w1.y + r.z*w1.z + r.w*w1.w;
    }
    #pragma unroll
    for (int o = 16; o; o >>= 1) {
        a0 += __shfl_xor_sync(0xffffffffu, a0, o);
        a1 += __shfl_xor_sync(0xffffffffu, a1, o);
    }

    if (lane < 2) {
        int h = lane;
        int s = src[e], d = dst[e];
        float td = edge_ts[e] - node_ts[s];
        float u  = (td + 1.0f) * ((float)TBL * 0.5f);
        u = fminf(fmaxf(u, 0.0f), (float)TBL - 0.001f);
        int   i  = (int)u;
        float fr = u - (float)i;
        float4 t = g_tbl[i];
        float te = h ? fmaf(t.w, fr, t.y) : fmaf(t.z, fr, t.x);
        float ee = (h ? a1 : a0) + te;                 // includes b_e (baked)
        float2 el2 = g_el[s];
        float elp  = (h ? el2.y : el2.x) + ee;         // el_prime (pre-leaky)
        float2 er2 = g_er[d];
        float ev   = elp + (h ? er2.y : er2.x);
        ev = ev > 0.f ? ev : 0.2f * ev;                // leaky relu
        float p = expf(ev);                            // |ev| small: no centering needed
        atomicAdd(&g_den[2 * d + h], p);
        atomicAdd(&g_num[2 * d + h], p * elp);
    }
}

// ---------------- pass 3: output --------------------------------------------
__global__ void out_kernel(const float* __restrict__ memory, float* __restrict__ out) {
    int idx = blockIdx.x * blockDim.x + threadIdx.x;
    if (idx >= NN * NF) return;
    int n = idx / NF;
    float d0 = g_den[2 * n], d1 = g_den[2 * n + 1];
    float ft0 = d0 > 0.f ? g_num[2 * n]     / d0 : 0.f;
    float ft1 = d1 > 0.f ? g_num[2 * n + 1] / d1 : 0.f;
    out[idx] = memory[idx] + 0.5f * (ft0 + ft1);
}

// ---------------- launch -----------------------------------------------------
extern "C" void kernel_launch(void* const* d_in, const int* in_sizes, int n_in,
                              void* d_out, int out_size) {
    const float* memory    = (const float*)d_in[0];
    const float* node_ts   = (const float*)d_in[1];
    const float* raw       = (const float*)d_in[2];
    const float* edge_ts   = (const float*)d_in[3];
    const float* time_w    = (const float*)d_in[4];
    const float* time_b    = (const float*)d_in[5];
    const float* fc_node_w = (const float*)d_in[6];
    const float* fc_node_b = (const float*)d_in[7];
    const float* fc_edge_w = (const float*)d_in[8];
    const float* fc_edge_b = (const float*)d_in[9];
    const float* attn_l    = (const float*)d_in[10];
    const float* attn_r    = (const float*)d_in[11];
    const float* attn_e    = (const float*)d_in[12];
    const int*   src       = (const int*)d_in[13];
    const int*   dst       = (const int*)d_in[14];
    float* out = (float*)d_out;

    prep_kernel<<<1, 256>>>(fc_node_w, fc_node_b, fc_edge_w, fc_edge_b,
                            attn_l, attn_r, attn_e);
    table_kernel<<<(TBL + 1 + 255) / 256, 256>>>(time_w, time_b);
    init_kernel<<<(2 * NN + 255) / 256, 256>>>();
    node_kernel<<<(NN * 32 + 255) / 256, 256>>>(memory);
    edge_kernel<<<(NE * 32 + 255) / 256, 256>>>(raw, edge_ts, node_ts, src, dst);
    out_kernel<<<(NN * NF + 255) / 256, 256>>>(memory, out);
}

// round 5
// speedup vs baseline: 1.8256x; 1.8256x over previous
#include <cuda_runtime.h>
#include <math.h>

#define NN   50000
#define NE   800000
#define NF   100
#define TDIM 100
#define TBL  8192
#define EPW  8          // edges per warp
#define NPW  4          // nodes per warp

// ---------------- scratch (static __device__, no allocation) ----------------
__device__ float4 g_wl0[25], g_wl1[25], g_wr0[25], g_wr1[25];   // node attn-folded weights
__device__ float4 g_we0[25], g_we1[25];                         // edge raw-feature folded weights
__device__ float  g_weT0[TDIM], g_weT1[TDIM];                   // temporal folded weights
__device__ float  g_bl[2], g_br[2], g_be[2];
__device__ float4 g_tbl[TBL + 1];                               // {g0(x), g1(x), dg0, dg1} (b_e baked in)
__device__ float4 g_elts[NN];                                   // {el0, el1, node_ts, 0}
__device__ float2 g_er[NN];
__device__ float4 g_acc[NN];                                    // {den0, num0, den1, num1}

// ---------------- pass 0: fold attention vectors into fc weights ------------
__global__ void prep_kernel(const float* __restrict__ fc_node_w,
                            const float* __restrict__ fc_node_b,
                            const float* __restrict__ fc_edge_w,
                            const float* __restrict__ fc_edge_b,
                            const float* __restrict__ attn_l,
                            const float* __restrict__ attn_r,
                            const float* __restrict__ attn_e) {
    int t = blockIdx.x * blockDim.x + threadIdx.x;
    if (t >= 806) return;
    if (t < 200) {                                   // w_l [100][2]
        int k = t >> 1, h = t & 1;
        const float* wr = fc_node_w + k * 200 + h * 100;
        const float* a  = attn_l + h * 100;
        float s = 0.f;
        for (int f = 0; f < 100; f++) s += wr[f] * a[f];
        ((float*)(h ? g_wl1 : g_wl0))[k] = s;
    } else if (t < 400) {                            // w_r [100][2]
        int k = (t - 200) >> 1, h = t & 1;
        const float* wr = fc_node_w + k * 200 + h * 100;
        const float* a  = attn_r + h * 100;
        float s = 0.f;
        for (int f = 0; f < 100; f++) s += wr[f] * a[f];
        ((float*)(h ? g_wr1 : g_wr0))[k] = s;
    } else if (t < 800) {                            // w_e [200][2]
        int k = (t - 400) >> 1, h = t & 1;
        const float* wr = fc_edge_w + k * 200 + h * 100;
        const float* a  = attn_e + h * 100;
        float s = 0.f;
        for (int f = 0; f < 100; f++) s += wr[f] * a[f];
        if (k < 100) ((float*)(h ? g_we1 : g_we0))[k] = s;
        else         (h ? g_weT1 : g_weT0)[k - 100] = s;
    } else {                                         // biases folded
        int u = t - 800, h = u & 1;
        float s = 0.f;
        if (u < 2)      { for (int f = 0; f < 100; f++) s += fc_node_b[h*100+f] * attn_l[h*100+f]; g_bl[h] = s; }
        else if (u < 4) { for (int f = 0; f < 100; f++) s += fc_node_b[h*100+f] * attn_r[h*100+f]; g_br[h] = s; }
        else            { for (int f = 0; f < 100; f++) s += fc_edge_b[h*100+f] * attn_e[h*100+f]; g_be[h] = s; }
    }
}

// ---------------- pass 0b: temporal lookup table ----------------------------
__global__ void table_kernel(const float* __restrict__ time_w,
                             const float* __restrict__ time_b) {
    int i = blockIdx.x * blockDim.x + threadIdx.x;
    if (i > TBL) return;
    const float dx = 2.0f / (float)TBL;
    float x  = -1.0f + i * dx;
    float x2 = x + dx;
    float v0 = 0.f, v1 = 0.f, u0 = 0.f, u1 = 0.f;
    for (int j = 0; j < TDIM; j++) {
        float w = time_w[j], b = time_b[j];
        float c  = cosf(x  * w + b);
        float c2 = cosf(x2 * w + b);
        float e0 = g_weT0[j], e1 = g_weT1[j];
        v0 += c  * e0; v1 += c  * e1;
        u0 += c2 * e0; u1 += c2 * e1;
    }
    float b0 = g_be[0], b1 = g_be[1];
    g_tbl[i] = make_float4(v0 + b0, v1 + b1, u0 - v0, u1 - v1);
}

// ---------------- pass 0c: zero accumulators --------------------------------
__global__ void init_kernel() {
    int i = blockIdx.x * blockDim.x + threadIdx.x;
    if (i < NN) g_acc[i] = make_float4(0.f, 0.f, 0.f, 0.f);
}

// ---------------- pass 1: per-node el/er (4 nodes per warp) -----------------
__global__ void node_kernel(const float* __restrict__ memory,
                            const float* __restrict__ node_ts) {
    int warp = (blockIdx.x * blockDim.x + threadIdx.x) >> 5;
    int lane = threadIdx.x & 31;
    int n0 = warp * NPW;
    if (n0 >= NN) return;
    float4 z = make_float4(0.f, 0.f, 0.f, 0.f);
    float4 wl0 = z, wl1 = z, wr0 = z, wr1 = z;
    if (lane < 25) { wl0 = g_wl0[lane]; wl1 = g_wl1[lane];
                     wr0 = g_wr0[lane]; wr1 = g_wr1[lane]; }
    float4 m[NPW];
    #pragma unroll
    for (int j = 0; j < NPW; j++)
        m[j] = (lane < 25) ? ((const float4*)(memory + (size_t)(n0 + j) * NF))[lane] : z;

    float l0[NPW], l1[NPW], r0[NPW], r1[NPW];
    #pragma unroll
    for (int j = 0; j < NPW; j++) {
        l0[j] = m[j].x*wl0.x + m[j].y*wl0.y + m[j].z*wl0.z + m[j].w*wl0.w;
        l1[j] = m[j].x*wl1.x + m[j].y*wl1.y + m[j].z*wl1.z + m[j].w*wl1.w;
        r0[j] = m[j].x*wr0.x + m[j].y*wr0.y + m[j].z*wr0.z + m[j].w*wr0.w;
        r1[j] = m[j].x*wr1.x + m[j].y*wr1.y + m[j].z*wr1.z + m[j].w*wr1.w;
    }
    #pragma unroll
    for (int o = 16; o; o >>= 1)
        #pragma unroll
        for (int j = 0; j < NPW; j++) {
            l0[j] += __shfl_xor_sync(0xffffffffu, l0[j], o);
            l1[j] += __shfl_xor_sync(0xffffffffu, l1[j], o);
            r0[j] += __shfl_xor_sync(0xffffffffu, r0[j], o);
            r1[j] += __shfl_xor_sync(0xffffffffu, r1[j], o);
        }
    if (lane < NPW) {
        // select this lane's node values without dynamic register indexing
        float vl0 = l0[0], vl1 = l1[0], vr0 = r0[0], vr1 = r1[0];
        #pragma unroll
        for (int j = 1; j < NPW; j++)
            if (lane == j) { vl0 = l0[j]; vl1 = l1[j]; vr0 = r0[j]; vr1 = r1[j]; }
        int n = n0 + lane;
        float ts = node_ts[n];
        g_elts[n] = make_float4(vl0 + g_bl[0], vl1 + g_bl[1], ts, 0.f);
        g_er[n]   = make_float2(vr0 + g_br[0], vr1 + g_br[1]);
    }
}

// ---------------- pass 2: edge sweep (8 edges per warp) ---------------------
__global__ void edge_kernel(const float* __restrict__ raw,
                            const float* __restrict__ edge_ts,
                            const int*   __restrict__ src,
                            const int*   __restrict__ dst) {
    int warp = (blockIdx.x * blockDim.x + threadIdx.x) >> 5;
    int lane = threadIdx.x & 31;
    long e0 = (long)warp * EPW;
    if (e0 >= NE) return;

    float4 z = make_float4(0.f, 0.f, 0.f, 0.f);
    float4 w0 = z, w1 = z;
    if (lane < 25) { w0 = g_we0[lane]; w1 = g_we1[lane]; }

    float4 r[EPW];
    #pragma unroll
    for (int j = 0; j < EPW; j++)
        r[j] = (lane < 25) ? ((const float4*)(raw + (e0 + j) * NF))[lane] : z;

    float a0[EPW], a1[EPW];
    #pragma unroll
    for (int j = 0; j < EPW; j++) {
        a0[j] = r[j].x*w0.x + r[j].y*w0.y + r[j].z*w0.z + r[j].w*w0.w;
        a1[j] = r[j].x*w1.x + r[j].y*w1.y + r[j].z*w1.z + r[j].w*w1.w;
    }
    #pragma unroll
    for (int o = 16; o; o >>= 1)
        #pragma unroll
        for (int j = 0; j < EPW; j++) {
            a0[j] += __shfl_xor_sync(0xffffffffu, a0[j], o);
            a1[j] += __shfl_xor_sync(0xffffffffu, a1[j], o);
        }

    if (lane < EPW) {
        float av0 = a0[0], av1 = a1[0];
        #pragma unroll
        for (int j = 1; j < EPW; j++)
            if (lane == j) { av0 = a0[j]; av1 = a1[j]; }

        long e = e0 + lane;
        int s = src[e], d = dst[e];
        float4 el4 = g_elts[s];                        // {el0, el1, ts_s, 0}
        float td = edge_ts[e] - el4.z;
        float u  = (td + 1.0f) * ((float)TBL * 0.5f);
        u = fminf(fmaxf(u, 0.0f), (float)TBL - 0.001f);
        int   i  = (int)u;
        float fr = u - (float)i;
        float4 t = g_tbl[i];
        float te0 = fmaf(t.z, fr, t.x);
        float te1 = fmaf(t.w, fr, t.y);
        float elp0 = el4.x + av0 + te0;                // el_prime head 0
        float elp1 = el4.y + av1 + te1;                // el_prime head 1
        float2 er2 = g_er[d];
        float ev0 = elp0 + er2.x;
        float ev1 = elp1 + er2.y;
        ev0 = ev0 > 0.f ? ev0 : 0.2f * ev0;            // leaky relu
        ev1 = ev1 > 0.f ? ev1 : 0.2f * ev1;
        float p0 = __expf(ev0);
        float p1 = __expf(ev1);
        float n0v = p0 * elp0;
        float n1v = p1 * elp1;
        asm volatile("red.global.add.v4.f32 [%0], {%1, %2, %3, %4};"
                     :: "l"(&g_acc[d]), "f"(p0), "f"(n0v), "f"(p1), "f"(n1v)
                     : "memory");
    }
}

// ---------------- pass 3: output (float4 per thread) ------------------------
__global__ void out_kernel(const float4* __restrict__ mem4, float4* __restrict__ out4) {
    int idx = blockIdx.x * blockDim.x + threadIdx.x;
    if (idx >= NN * (NF / 4)) return;
    int n = idx / (NF / 4);
    float4 acc = g_acc[n];
    float ft = (acc.x > 0.f ? acc.y / acc.x : 0.f)
             + (acc.z > 0.f ? acc.w / acc.z : 0.f);
    float add = 0.5f * ft;
    float4 m = mem4[idx];
    out4[idx] = make_float4(m.x + add, m.y + add, m.z + add, m.w + add);
}

// ---------------- launch -----------------------------------------------------
extern "C" void kernel_launch(void* const* d_in, const int* in_sizes, int n_in,
                              void* d_out, int out_size) {
    const float* memory    = (const float*)d_in[0];
    const float* node_ts   = (const float*)d_in[1];
    const float* raw       = (const float*)d_in[2];
    const float* edge_ts   = (const float*)d_in[3];
    const float* time_w    = (const float*)d_in[4];
    const float* time_b    = (const float*)d_in[5];
    const float* fc_node_w = (const float*)d_in[6];
    const float* fc_node_b = (const float*)d_in[7];
    const float* fc_edge_w = (const float*)d_in[8];
    const float* fc_edge_b = (const float*)d_in[9];
    const float* attn_l    = (const float*)d_in[10];
    const float* attn_r    = (const float*)d_in[11];
    const float* attn_e    = (const float*)d_in[12];
    const int*   src       = (const int*)d_in[13];
    const int*   dst       = (const int*)d_in[14];
    float* out = (float*)d_out;

    prep_kernel<<<7, 128>>>(fc_node_w, fc_node_b, fc_edge_w, fc_edge_b,
                            attn_l, attn_r, attn_e);
    table_kernel<<<(TBL + 1 + 255) / 256, 256>>>(time_w, time_b);
    init_kernel<<<(NN + 255) / 256, 256>>>();
    node_kernel<<<((NN / NPW) * 32 + 255) / 256, 256>>>(memory, node_ts);
    edge_kernel<<<((NE / EPW) * 32) / 256, 256>>>(raw, edge_ts, src, dst);
    out_kernel<<<(NN * (NF / 4) + 255) / 256, 256>>>((const float4*)memory, (float4*)out);
}